// round 4
// baseline (speedup 1.0000x reference)
#include <cuda_runtime.h>
#include <math_constants.h>

// Problem constants (dataset-fixed): N = 262144 rows, C = 1000 classes.
// Scratch for deterministic two-stage reduction (no atomics -> bitwise
// reproducible across graph replays).
#define CE_NMAX 262144
#define CE_NPART 256

__device__ float g_row_loss[CE_NMAX];
__device__ float g_partials[CE_NPART];

// ---------------------------------------------------------------------------
// Kernel 1: one CTA (256 threads) per row.
//   thread t (t < ceil(C/4)) loads logits[row, 4t..4t+3] as one LDG.128 (.cs)
//   -> block max -> block sum of __expf(x - max) -> loss = log(sum)+max - x[label]
// The label logit is grabbed from the register of the thread that loaded it,
// so the row is read from DRAM exactly once.
// ---------------------------------------------------------------------------
__global__ __launch_bounds__(256, 8)
void ce_row_kernel(const float* __restrict__ logits,
                   const long long* __restrict__ labels,
                   int C)
{
    const int row  = blockIdx.x;
    const int tid  = threadIdx.x;
    const int lane = tid & 31;
    const int warp = tid >> 5;

    const float* rowp = logits + (long long)row * (long long)C;

    __shared__ float s_red[8];
    __shared__ float s_sum[8];
    __shared__ int   s_label;
    __shared__ float s_label_logit;

    if (tid == 0) s_label = (int)labels[row];

    // ---- load up to 4 contiguous floats (vectorized when fully in-range) ----
    float4 v = make_float4(-CUDART_INF_F, -CUDART_INF_F, -CUDART_INF_F, -CUDART_INF_F);
    const int base = tid << 2;
    if (base + 3 < C) {
        v = __ldcs(reinterpret_cast<const float4*>(rowp + base));
    } else if (base < C) {
        float* pv = reinterpret_cast<float*>(&v);
        #pragma unroll
        for (int i = 0; i < 4; ++i)
            if (base + i < C) pv[i] = __ldcs(rowp + base + i);
    }

    __syncthreads();                         // s_label visible to all
    const int lab = s_label;
    if ((lab >> 2) == tid) {                 // this thread holds logits[row, lab]
        s_label_logit = reinterpret_cast<const float*>(&v)[lab & 3];
    }

    // ---- block max ----
    float m = fmaxf(fmaxf(v.x, v.y), fmaxf(v.z, v.w));
    #pragma unroll
    for (int off = 16; off > 0; off >>= 1)
        m = fmaxf(m, __shfl_xor_sync(0xffffffffu, m, off));
    if (lane == 0) s_red[warp] = m;
    __syncthreads();
    if (tid < 8) {
        float mm = s_red[tid];
        #pragma unroll
        for (int off = 4; off > 0; off >>= 1)
            mm = fmaxf(mm, __shfl_xor_sync(0x000000ffu, mm, off));
        if (tid == 0) s_red[0] = mm;
    }
    __syncthreads();
    const float rowmax = s_red[0];

    // ---- block sum of exp(x - max); -INF lanes contribute exp(-inf)=0 ----
    float s = __expf(v.x - rowmax) + __expf(v.y - rowmax)
            + __expf(v.z - rowmax) + __expf(v.w - rowmax);
    #pragma unroll
    for (int off = 16; off > 0; off >>= 1)
        s += __shfl_xor_sync(0xffffffffu, s, off);
    if (lane == 0) s_sum[warp] = s;
    __syncthreads();
    if (tid < 8) {
        float ss = s_sum[tid];
        #pragma unroll
        for (int off = 4; off > 0; off >>= 1)
            ss += __shfl_xor_sync(0x000000ffu, ss, off);
        if (tid == 0) {
            // positive per-row loss = -logp[label] = log(sumexp) + max - x_label
            g_row_loss[row] = __logf(ss) + rowmax - s_label_logit;
        }
    }
}

// ---------------------------------------------------------------------------
// Block-sum helper (256 threads)
// ---------------------------------------------------------------------------
__device__ __forceinline__ float block_sum_256(float s)
{
    __shared__ float sh[8];
    const int lane = threadIdx.x & 31;
    const int warp = threadIdx.x >> 5;
    #pragma unroll
    for (int off = 16; off > 0; off >>= 1)
        s += __shfl_xor_sync(0xffffffffu, s, off);
    if (lane == 0) sh[warp] = s;
    __syncthreads();
    float r = 0.0f;
    if (threadIdx.x < 8) {
        r = sh[threadIdx.x];
        #pragma unroll
        for (int off = 4; off > 0; off >>= 1)
            r += __shfl_xor_sync(0x000000ffu, r, off);
    }
    return r;  // valid in thread 0
}

// ---------------------------------------------------------------------------
// Kernel 2: 256 blocks x 256 threads, grid-stride sum of g_row_loss -> partials
// ---------------------------------------------------------------------------
__global__ __launch_bounds__(256)
void ce_reduce1_kernel(int n)
{
    float s = 0.0f;
    const int stride = gridDim.x * blockDim.x;
    for (int i = blockIdx.x * blockDim.x + threadIdx.x; i < n; i += stride)
        s += g_row_loss[i];
    const float bs = block_sum_256(s);
    if (threadIdx.x == 0) g_partials[blockIdx.x] = bs;
}

// ---------------------------------------------------------------------------
// Kernel 3: single block folds 256 partials -> mean loss = +sum / N
// (reference = -sum(logp[label])/N, and g_row_loss already holds -logp.)
// ---------------------------------------------------------------------------
__global__ __launch_bounds__(256)
void ce_reduce2_kernel(float* __restrict__ out, int n)
{
    float s = g_partials[threadIdx.x];
    const float bs = block_sum_256(s);
    if (threadIdx.x == 0) out[0] = bs / (float)n;
}

// ---------------------------------------------------------------------------
extern "C" void kernel_launch(void* const* d_in, const int* in_sizes, int n_in,
                              void* d_out, int out_size)
{
    const float*     logits = (const float*)d_in[0];
    const long long* labels = (const long long*)d_in[1];
    float*           out    = (float*)d_out;

    const int N = in_sizes[1];                 // 262144
    const int C = in_sizes[0] / N;             // 1000

    ce_row_kernel<<<N, 256>>>(logits, labels, C);
    ce_reduce1_kernel<<<CE_NPART, 256>>>(N);
    ce_reduce2_kernel<<<1, 256>>>(out, N);
}

// round 7
// speedup vs baseline: 2.1710x; 2.1710x over previous
#include <cuda_runtime.h>
#include <math_constants.h>

// Problem constants (dataset-fixed): N = 262144 rows, C = 1000 classes.
#define CE_NMAX 262144
#define CE_NPART 256

__device__ float g_row_loss[CE_NMAX];
__device__ float g_partials[CE_NPART];

// ---------------------------------------------------------------------------
// Specialized kernel for C == 1000: ONE WARP per row.
// Lane l owns cols {k*128 + l*4 .. +3} for k = 0..7.
//   k < 7           : always in-bounds (max col 895+3? no: 768+124+3 = 895 < 1000)  -> unconditional LDG.128
//   k = 7, lane < 26: base = 896+4l <= 996, base+3 = 999 -> in-bounds LDG.128
//   k = 7, lane >= 26: fill -INF
// No smem, no __syncthreads, no scalar tail, no gather: the label logit is
// extracted from the registers that already hold it (select chain + shfl).
// ---------------------------------------------------------------------------
__global__ __launch_bounds__(256, 4)
void ce_warp_c1000_kernel(const float* __restrict__ logits,
                          const long long* __restrict__ labels,
                          int N)
{
    const int lane = threadIdx.x & 31;
    const int warp = threadIdx.x >> 5;
    const int row  = (blockIdx.x << 3) + warp;   // 8 warps per CTA
    if (row >= N) return;                        // whole warp uniform

    const float* rowp = logits + (long long)row * 1000LL;

    // Uniform label load (all lanes same address -> one transaction).
    const int lab = (int)labels[row];

    // --- front-batched bulk load: 8 float4 per lane, compile-time bounds ---
    float4 v[8];
    #pragma unroll
    for (int k = 0; k < 7; ++k)
        v[k] = __ldcs(reinterpret_cast<const float4*>(rowp + (k << 7) + (lane << 2)));
    if (lane < 26)
        v[7] = __ldcs(reinterpret_cast<const float4*>(rowp + 896 + (lane << 2)));
    else
        v[7] = make_float4(-CUDART_INF_F, -CUDART_INF_F,
                           -CUDART_INF_F, -CUDART_INF_F);

    // --- label logit from registers: owner lane = (lab>>2)&31, chunk lab>>7 ---
    const int klab = lab >> 7;
    const int elab = lab & 3;
    const int slab = (lab >> 2) & 31;
    float4 w = v[0];
    #pragma unroll
    for (int k = 1; k < 8; ++k)
        if (klab == k) w = v[k];                 // SELs, keeps v in registers
    float val = (elab == 0) ? w.x : (elab == 1) ? w.y : (elab == 2) ? w.z : w.w;
    const float xlab = __shfl_sync(0xffffffffu, val, slab);

    // --- warp max ---
    float m = -CUDART_INF_F;
    #pragma unroll
    for (int k = 0; k < 8; ++k)
        m = fmaxf(m, fmaxf(fmaxf(v[k].x, v[k].y), fmaxf(v[k].z, v[k].w)));
    #pragma unroll
    for (int off = 16; off > 0; off >>= 1)
        m = fmaxf(m, __shfl_xor_sync(0xffffffffu, m, off));

    // --- warp sum of exp(x - m); -INF fills contribute 0 ---
    float s = 0.0f;
    #pragma unroll
    for (int k = 0; k < 8; ++k)
        s += __expf(v[k].x - m) + __expf(v[k].y - m)
           + __expf(v[k].z - m) + __expf(v[k].w - m);
    #pragma unroll
    for (int off = 16; off > 0; off >>= 1)
        s += __shfl_xor_sync(0xffffffffu, s, off);

    if (lane == 0)
        g_row_loss[row] = __logf(s) + m - xlab;  // positive loss = -logp[label]
}

// ---------------------------------------------------------------------------
// Generic fallback (any C): warp per row, online softmax, scalar loads.
// Correctness-only path; the benched shape always takes the C==1000 kernel.
// ---------------------------------------------------------------------------
__global__ __launch_bounds__(256)
void ce_warp_generic_kernel(const float* __restrict__ logits,
                            const long long* __restrict__ labels,
                            int C, int N)
{
    const int lane = threadIdx.x & 31;
    const int warp = threadIdx.x >> 5;
    const int row  = (blockIdx.x << 3) + warp;
    if (row >= N) return;

    const float* rowp = logits + (long long)row * (long long)C;
    const int lab = (int)labels[row];

    float m = -CUDART_INF_F, s = 0.0f;
    for (int col = lane; col < C; col += 32) {
        const float x = rowp[col];
        const float mn = fmaxf(m, x);
        s = s * __expf(m - mn) + __expf(x - mn);
        m = mn;
    }
    // combine (m, s) across the warp
    #pragma unroll
    for (int off = 16; off > 0; off >>= 1) {
        const float mo = __shfl_xor_sync(0xffffffffu, m, off);
        const float so = __shfl_xor_sync(0xffffffffu, s, off);
        const float mn = fmaxf(m, mo);
        s = s * __expf(m - mn) + so * __expf(mo - mn);
        m = mn;
    }
    float xlab = 0.0f;
    if (lane == 0) xlab = rowp[lab];
    if (lane == 0)
        g_row_loss[row] = __logf(s) + m - xlab;
}

// ---------------------------------------------------------------------------
// Block-sum helper (256 threads)
// ---------------------------------------------------------------------------
__device__ __forceinline__ float block_sum_256(float s)
{
    __shared__ float sh[8];
    const int lane = threadIdx.x & 31;
    const int warp = threadIdx.x >> 5;
    #pragma unroll
    for (int off = 16; off > 0; off >>= 1)
        s += __shfl_xor_sync(0xffffffffu, s, off);
    if (lane == 0) sh[warp] = s;
    __syncthreads();
    float r = 0.0f;
    if (threadIdx.x < 8) {
        r = sh[threadIdx.x];
        #pragma unroll
        for (int off = 4; off > 0; off >>= 1)
            r += __shfl_xor_sync(0x000000ffu, r, off);
    }
    return r;  // valid in thread 0
}

// ---------------------------------------------------------------------------
// Kernel 2: 256 blocks x 256 threads, grid-stride sum of g_row_loss -> partials
// ---------------------------------------------------------------------------
__global__ __launch_bounds__(256)
void ce_reduce1_kernel(int n)
{
    float s = 0.0f;
    const int stride = gridDim.x * blockDim.x;
    for (int i = blockIdx.x * blockDim.x + threadIdx.x; i < n; i += stride)
        s += g_row_loss[i];
    const float bs = block_sum_256(s);
    if (threadIdx.x == 0) g_partials[blockIdx.x] = bs;
}

// ---------------------------------------------------------------------------
// Kernel 3: single block folds 256 partials -> mean loss = +sum / N
// ---------------------------------------------------------------------------
__global__ __launch_bounds__(256)
void ce_reduce2_kernel(float* __restrict__ out, int n)
{
    float s = g_partials[threadIdx.x];
    const float bs = block_sum_256(s);
    if (threadIdx.x == 0) out[0] = bs / (float)n;
}

// ---------------------------------------------------------------------------
extern "C" void kernel_launch(void* const* d_in, const int* in_sizes, int n_in,
                              void* d_out, int out_size)
{
    const float*     logits = (const float*)d_in[0];
    const long long* labels = (const long long*)d_in[1];
    float*           out    = (float*)d_out;

    const int N = in_sizes[1];                 // 262144
    const int C = in_sizes[0] / N;             // 1000

    const int grid = (N + 7) / 8;              // 8 warps (rows) per CTA
    if (C == 1000)
        ce_warp_c1000_kernel<<<grid, 256>>>(logits, labels, N);
    else
        ce_warp_generic_kernel<<<grid, 256>>>(logits, labels, C, N);

    ce_reduce1_kernel<<<CE_NPART, 256>>>(N);
    ce_reduce2_kernel<<<1, 256>>>(out, N);
}

// round 8
// speedup vs baseline: 2.2191x; 1.0221x over previous
#include <cuda_runtime.h>
#include <math_constants.h>

// Problem constants (dataset-fixed): N = 262144 rows, C = 1000 classes.
#define CE_MAXCTAS 65536   // >= ceil(N/8) for the benched shape (32768)

__device__ float g_cta_loss[CE_MAXCTAS];

// ---------------------------------------------------------------------------
// Specialized kernel for C == 1000: ONE WARP per row, 8 rows per CTA.
// Lane l owns cols {k*128 + l*4 .. +3}, k = 0..7 (compile-time bounds for
// C=1000: k<7 always in-bounds, k=7 in-bounds iff lane<26).
// All 8 LDG.128 front-batched (MLP=8), evict-first (.cs). Label logit is
// extracted from the registers that already hold it (SEL chain + shfl) — no
// gather load. Epilogue: per-CTA block sum of the 8 row losses (hidden under
// the DRAM drain of neighbouring CTAs).
// ---------------------------------------------------------------------------
__global__ __launch_bounds__(256, 4)
void ce_warp_c1000_kernel(const float* __restrict__ logits,
                          const long long* __restrict__ labels,
                          int N)
{
    const int lane = threadIdx.x & 31;
    const int warp = threadIdx.x >> 5;
    const int row  = (blockIdx.x << 3) + warp;   // 8 warps per CTA

    __shared__ float sh[8];

    float rowloss = 0.0f;
    if (row < N) {
        const float* rowp = logits + (long long)row * 1000LL;

        // Uniform label load (all lanes same address -> one transaction).
        const int lab = (int)labels[row];

        // --- front-batched bulk load: 8 float4 per lane ---
        float4 v[8];
        #pragma unroll
        for (int k = 0; k < 7; ++k)
            v[k] = __ldcs(reinterpret_cast<const float4*>(rowp + (k << 7) + (lane << 2)));
        if (lane < 26)
            v[7] = __ldcs(reinterpret_cast<const float4*>(rowp + 896 + (lane << 2)));
        else
            v[7] = make_float4(-CUDART_INF_F, -CUDART_INF_F,
                               -CUDART_INF_F, -CUDART_INF_F);

        // --- label logit from registers ---
        const int klab = lab >> 7;
        const int elab = lab & 3;
        const int slab = (lab >> 2) & 31;
        float4 w = v[0];
        #pragma unroll
        for (int k = 1; k < 8; ++k)
            if (klab == k) w = v[k];
        float val = (elab == 0) ? w.x : (elab == 1) ? w.y : (elab == 2) ? w.z : w.w;
        const float xlab = __shfl_sync(0xffffffffu, val, slab);

        // --- warp max ---
        float m = -CUDART_INF_F;
        #pragma unroll
        for (int k = 0; k < 8; ++k)
            m = fmaxf(m, fmaxf(fmaxf(v[k].x, v[k].y), fmaxf(v[k].z, v[k].w)));
        #pragma unroll
        for (int off = 16; off > 0; off >>= 1)
            m = fmaxf(m, __shfl_xor_sync(0xffffffffu, m, off));

        // --- warp sum of exp(x - m); -INF fills contribute 0 ---
        float s = 0.0f;
        #pragma unroll
        for (int k = 0; k < 8; ++k)
            s += __expf(v[k].x - m) + __expf(v[k].y - m)
               + __expf(v[k].z - m) + __expf(v[k].w - m);
        #pragma unroll
        for (int off = 16; off > 0; off >>= 1)
            s += __shfl_xor_sync(0xffffffffu, s, off);

        rowloss = __logf(s) + m - xlab;          // positive loss = -logp[label]
    }

    // --- per-CTA sum of 8 row losses ---
    if (lane == 0) sh[warp] = rowloss;
    __syncthreads();
    if (threadIdx.x == 0) {
        float c = 0.0f;
        #pragma unroll
        for (int k = 0; k < 8; ++k) c += sh[k];
        g_cta_loss[blockIdx.x] = c;
    }
}

// ---------------------------------------------------------------------------
// Generic fallback (any C): warp per row, online softmax, scalar loads.
// Same per-CTA-sum epilogue. Correctness-only path.
// ---------------------------------------------------------------------------
__global__ __launch_bounds__(256)
void ce_warp_generic_kernel(const float* __restrict__ logits,
                            const long long* __restrict__ labels,
                            int C, int N)
{
    const int lane = threadIdx.x & 31;
    const int warp = threadIdx.x >> 5;
    const int row  = (blockIdx.x << 3) + warp;

    __shared__ float sh[8];

    float rowloss = 0.0f;
    if (row < N) {
        const float* rowp = logits + (long long)row * (long long)C;
        const int lab = (int)labels[row];

        float m = -CUDART_INF_F, s = 0.0f;
        for (int col = lane; col < C; col += 32) {
            const float x = rowp[col];
            const float mn = fmaxf(m, x);
            s = s * __expf(m - mn) + __expf(x - mn);
            m = mn;
        }
        #pragma unroll
        for (int off = 16; off > 0; off >>= 1) {
            const float mo = __shfl_xor_sync(0xffffffffu, m, off);
            const float so = __shfl_xor_sync(0xffffffffu, s, off);
            const float mn = fmaxf(m, mo);
            s = s * __expf(m - mn) + so * __expf(mo - mn);
            m = mn;
        }
        float xlab = 0.0f;
        if (lane == 0) xlab = rowp[lab];
        rowloss = __logf(s) + m - xlab;          // valid in lane 0
    }

    if (lane == 0) sh[warp] = rowloss;
    __syncthreads();
    if (threadIdx.x == 0) {
        float c = 0.0f;
        #pragma unroll
        for (int k = 0; k < 8; ++k) c += sh[k];
        g_cta_loss[blockIdx.x] = c;
    }
}

// ---------------------------------------------------------------------------
// Final kernel: ONE CTA of 1024 threads folds all per-CTA sums -> out = sum/N.
// For the benched shape: 32768 floats = 128 KB; each thread front-batches
// 8 x LDG.128 -> one DRAM latency round. Deterministic fixed-order tree.
// ---------------------------------------------------------------------------
__global__ __launch_bounds__(1024)
void ce_final_kernel(float* __restrict__ out, int nCTA, int N)
{
    const int tid = threadIdx.x;
    float s = 0.0f;

    const int nvec = nCTA >> 2;                  // float4 count
    const float4* p4 = reinterpret_cast<const float4*>(g_cta_loss);
    for (int i = tid; i < nvec; i += 1024) {
        const float4 u = p4[i];
        s += (u.x + u.y) + (u.z + u.w);
    }
    for (int i = (nvec << 2) + tid; i < nCTA; i += 1024)
        s += g_cta_loss[i];

    // block sum (1024 threads = 32 warps)
    __shared__ float sh[32];
    const int lane = tid & 31;
    const int warp = tid >> 5;
    #pragma unroll
    for (int off = 16; off > 0; off >>= 1)
        s += __shfl_xor_sync(0xffffffffu, s, off);
    if (lane == 0) sh[warp] = s;
    __syncthreads();
    if (warp == 0) {
        float r = sh[lane];
        #pragma unroll
        for (int off = 16; off > 0; off >>= 1)
            r += __shfl_xor_sync(0xffffffffu, r, off);
        if (lane == 0) out[0] = r / (float)N;
    }
}

// ---------------------------------------------------------------------------
extern "C" void kernel_launch(void* const* d_in, const int* in_sizes, int n_in,
                              void* d_out, int out_size)
{
    const float*     logits = (const float*)d_in[0];
    const long long* labels = (const long long*)d_in[1];
    float*           out    = (float*)d_out;

    const int N = in_sizes[1];                 // 262144
    const int C = in_sizes[0] / N;             // 1000

    const int grid = (N + 7) / 8;              // 8 warps (rows) per CTA

    if (C == 1000)
        ce_warp_c1000_kernel<<<grid, 256>>>(logits, labels, N);
    else
        ce_warp_generic_kernel<<<grid, 256>>>(logits, labels, C, N);

    ce_final_kernel<<<1, 1024>>>(out, grid, N);
}